// round 1
// baseline (speedup 1.0000x reference)
#include <cuda_runtime.h>
#include <math.h>

// Problem constants
#define VOCAB  50257
#define BB     32
#define TT     64
#define EE     256
#define HH     8
#define DD     32
#define LL     8
#define FFN    1024
#define NTOK   (BB*TT)          // 2048
#define EPSLN  1e-5f

// ---------------------------------------------------------------------------
// Scratch: one big __device__ buffer (no allocation allowed).
// Layout (float offsets):
//   x    : [2048,256]            @ 0
//   qkv  : [2048,768]            @ 524288
//   att  : [2048,256]            @ 2097152
//   h    : [2048,1024]           @ 2621440
//   y    : [2048,256]            @ 4718592
//   xf   : [2048,256]            @ 5242880
//   wt   : [8,256,768] qkv^T     @ 5767168
// total 7340032 floats (~29.4 MB)
// ---------------------------------------------------------------------------
#define OFF_X    0
#define OFF_QKV  524288
#define OFF_ATT  2097152
#define OFF_H    2621440
#define OFF_Y    4718592
#define OFF_XF   5242880
#define OFF_WT   5767168
#define BUF_TOTAL 7340032

__device__ float g_buf[BUF_TOTAL];

// ---------------------------------------------------------------------------
// Embedding: x[b,t,:] = tok_emb[ip[b,t]] + pos_emb[t]
// ---------------------------------------------------------------------------
__global__ void embed_kernel(const int* __restrict__ ip,
                             const float* __restrict__ tok,
                             const float* __restrict__ pos,
                             float* __restrict__ x) {
    int row = blockIdx.x;            // 0..2047
    int c   = threadIdx.x;           // 0..255
    int t   = row & (TT - 1);
    int v   = ip[row];
    x[row * EE + c] = tok[(size_t)v * EE + c] + pos[t * EE + c];
}

// ---------------------------------------------------------------------------
// One-time transpose of Wq/Wk/Wv [L,H,E,D] -> wt [L, E, 768]
// column j: j<256 -> q(h=j>>5,d=j&31), 256..511 -> k, 512..767 -> v
// ---------------------------------------------------------------------------
__global__ void prep_wqkv_kernel(const float* __restrict__ Wq,
                                 const float* __restrict__ Wk,
                                 const float* __restrict__ Wv) {
    int idx = blockIdx.x * blockDim.x + threadIdx.x;
    const int total = LL * EE * 768;
    if (idx >= total) return;
    int l = idx / (EE * 768);
    int r = idx % (EE * 768);
    int c = r / 768;
    int j = r % 768;
    int sel = j >> 8;
    int hd  = j & 255;
    int h = hd >> 5, d = hd & 31;
    const float* W = (sel == 0) ? Wq : (sel == 1) ? Wk : Wv;
    g_buf[OFF_WT + idx] = W[(((size_t)(l * HH + h) * EE + c) * DD) + d];
}

// ---------------------------------------------------------------------------
// Tiled SGEMM: C[M,N] = A[M,K] @ B[K,N] (+bias) (opt relu)
// ---------------------------------------------------------------------------
template<int BM, int BN, int BK, int TM, int TN, bool RELU>
__global__ void __launch_bounds__((BM/TM)*(BN/TN))
sgemm_kernel(int M, int N, int K,
             const float* __restrict__ A,
             const float* __restrict__ B,
             const float* __restrict__ bias,
             float* __restrict__ C) {
    __shared__ float As[BK][BM];
    __shared__ float Bs[BK][BN];

    constexpr int NTH = (BM/TM)*(BN/TN);
    const int tid  = threadIdx.x;
    const int tcol = tid % (BN/TN);
    const int trow = tid / (BN/TN);
    const int brow = blockIdx.y * BM;
    const int bcol = blockIdx.x * BN;

    float acc[TM][TN];
#pragma unroll
    for (int i = 0; i < TM; i++)
#pragma unroll
        for (int j = 0; j < TN; j++) acc[i][j] = 0.f;

    for (int k0 = 0; k0 < K; k0 += BK) {
        // A tile (BM x BK) -> As[k][m]
#pragma unroll
        for (int i = tid; i < BM*BK; i += NTH) {
            int r = i / BK, c = i % BK;
            int gr = brow + r;
            As[c][r] = (gr < M) ? A[(size_t)gr * K + k0 + c] : 0.f;
        }
        // B tile (BK x BN) -> Bs[k][n]
#pragma unroll
        for (int i = tid; i < BK*BN; i += NTH) {
            int r = i / BN, c = i % BN;
            int gc = bcol + c;
            Bs[r][c] = (gc < N) ? B[(size_t)(k0 + r) * N + gc] : 0.f;
        }
        __syncthreads();

#pragma unroll
        for (int kk = 0; kk < BK; kk++) {
            float a[TM], b[TN];
#pragma unroll
            for (int i = 0; i < TM; i++) a[i] = As[kk][trow*TM + i];
#pragma unroll
            for (int j = 0; j < TN; j++) b[j] = Bs[kk][tcol*TN + j];
#pragma unroll
            for (int i = 0; i < TM; i++)
#pragma unroll
                for (int j = 0; j < TN; j++)
                    acc[i][j] += a[i] * b[j];
        }
        __syncthreads();
    }

#pragma unroll
    for (int i = 0; i < TM; i++) {
        int gr = brow + trow*TM + i;
        if (gr >= M) continue;
#pragma unroll
        for (int j = 0; j < TN; j++) {
            int gc = bcol + tcol*TN + j;
            if (gc >= N) continue;
            float v = acc[i][j];
            if (bias) v += bias[gc];
            if (RELU) v = fmaxf(v, 0.f);
            C[(size_t)gr * N + gc] = v;
        }
    }
}

// ---------------------------------------------------------------------------
// Fused causal attention. grid = B*H blocks, 64 threads (one per query t).
// qkv: [2048,768] rows (b*T+t); q at col h*32+d, k at +256, v at +512.
// Output att: [2048, 256] with col = h*32 + d (head-concat layout).
// ---------------------------------------------------------------------------
__global__ void attn_kernel(const float* __restrict__ qkv,
                            float* __restrict__ att) {
    __shared__ float qs[TT][DD+1];
    __shared__ float ks[TT][DD+1];
    __shared__ float vs[TT][DD+1];
    __shared__ float ss[TT][TT+1];

    int bh = blockIdx.x;
    int b = bh / HH, h = bh % HH;
    int tid = threadIdx.x;  // 0..63

    const float* base = qkv + (size_t)b * TT * 768 + h * DD;
    for (int i = tid; i < TT * DD; i += TT) {
        int s = i >> 5, d = i & 31;
        qs[s][d] = base[s * 768 + d];
        ks[s][d] = base[s * 768 + 256 + d];
        vs[s][d] = base[s * 768 + 512 + d];
    }
    __syncthreads();

    const int t = tid;
    const float scale = 0.17677669529663687f;  // 1/sqrt(32)

    float m = -1e30f;
    for (int s = 0; s <= t; s++) {
        float acc = 0.f;
#pragma unroll
        for (int d = 0; d < DD; d++) acc += qs[t][d] * ks[s][d];
        acc *= scale;
        ss[t][s] = acc;
        m = fmaxf(m, acc);
    }
    float sum = 0.f;
    for (int s = 0; s <= t; s++) {
        float p = __expf(ss[t][s] - m);
        ss[t][s] = p;
        sum += p;
    }
    float inv = 1.f / sum;

    float o[DD];
#pragma unroll
    for (int d = 0; d < DD; d++) o[d] = 0.f;
    for (int s = 0; s <= t; s++) {
        float w = ss[t][s] * inv;
#pragma unroll
        for (int d = 0; d < DD; d++) o[d] += w * vs[s][d];
    }

    float* op = att + (size_t)(b * TT + t) * EE + h * DD;
#pragma unroll
    for (int d = 0; d < DD; d++) op[d] = o[d];
}

// ---------------------------------------------------------------------------
// LayerNorm (optionally with residual add): out = LN(xin (+ yin); g, b)
// One block per row, 256 threads (== E).
// ---------------------------------------------------------------------------
__global__ void ln_kernel(const float* __restrict__ xin,
                          const float* __restrict__ yin,
                          const float* __restrict__ g,
                          const float* __restrict__ b,
                          float* __restrict__ out) {
    __shared__ float red1[8];
    __shared__ float red2[8];
    int row = blockIdx.x;
    int c   = threadIdx.x;

    float v = xin[(size_t)row * EE + c];
    if (yin) v += yin[(size_t)row * EE + c];

    // mean
    float s = v;
#pragma unroll
    for (int o = 16; o > 0; o >>= 1) s += __shfl_xor_sync(0xffffffffu, s, o);
    if ((c & 31) == 0) red1[c >> 5] = s;
    __syncthreads();
    float total = 0.f;
#pragma unroll
    for (int i = 0; i < 8; i++) total += red1[i];
    float mean = total * (1.f / EE);

    // var
    float d = v - mean;
    float sq = d * d;
#pragma unroll
    for (int o = 16; o > 0; o >>= 1) sq += __shfl_xor_sync(0xffffffffu, sq, o);
    if ((c & 31) == 0) red2[c >> 5] = sq;
    __syncthreads();
    float tsq = 0.f;
#pragma unroll
    for (int i = 0; i < 8; i++) tsq += red2[i];
    float var = tsq * (1.f / EE);

    out[(size_t)row * EE + c] = d * rsqrtf(var + EPSLN) * g[c] + b[c];
}

// ---------------------------------------------------------------------------
// Host orchestration
// ---------------------------------------------------------------------------
extern "C" void kernel_launch(void* const* d_in, const int* in_sizes, int n_in,
                              void* d_out, int out_size) {
    const int*   ip     = (const int*)  d_in[0];
    const float* tok    = (const float*)d_in[1];
    const float* pos    = (const float*)d_in[2];
    const float* Wq     = (const float*)d_in[3];
    const float* Wk     = (const float*)d_in[4];
    const float* Wv     = (const float*)d_in[5];
    const float* Wo     = (const float*)d_in[6];
    const float* bo     = (const float*)d_in[7];
    const float* ln1g   = (const float*)d_in[8];
    const float* ln1b   = (const float*)d_in[9];
    const float* ln2g   = (const float*)d_in[10];
    const float* ln2b   = (const float*)d_in[11];
    const float* W1     = (const float*)d_in[12];
    const float* b1     = (const float*)d_in[13];
    const float* W2     = (const float*)d_in[14];
    const float* b2     = (const float*)d_in[15];
    const float* lnfg   = (const float*)d_in[16];
    const float* lnfb   = (const float*)d_in[17];
    const float* Wlm    = (const float*)d_in[18];
    const float* blm    = (const float*)d_in[19];
    float*       out    = (float*)d_out;

    float* buf = nullptr;
    cudaGetSymbolAddress((void**)&buf, g_buf);
    float* x    = buf + OFF_X;
    float* qkv  = buf + OFF_QKV;
    float* attb = buf + OFF_ATT;
    float* hbuf = buf + OFF_H;
    float* y    = buf + OFF_Y;
    float* xf   = buf + OFF_XF;
    float* wt   = buf + OFF_WT;

    // Embedding
    embed_kernel<<<NTOK, EE>>>(ip, tok, pos, x);

    // QKV weight transpose (cheap; re-run each replay, deterministic)
    {
        int total = LL * EE * 768;
        prep_wqkv_kernel<<<(total + 255) / 256, 256>>>(Wq, Wk, Wv);
    }

    // Layer loop
    for (int l = 0; l < LL; l++) {
        // QKV projection: [2048,256]@[256,768]
        {
            dim3 grid((768 + 63) / 64, (NTOK + 63) / 64);
            sgemm_kernel<64,64,16,4,4,false><<<grid, 256>>>(
                NTOK, 768, EE, x, wt + (size_t)l * EE * 768, nullptr, qkv);
        }
        // Attention
        attn_kernel<<<BB * HH, TT>>>(qkv, attb);
        // Output projection: [2048,256]@[256,256] + bo
        {
            dim3 grid((EE + 63) / 64, (NTOK + 63) / 64);
            sgemm_kernel<64,64,16,4,4,false><<<grid, 256>>>(
                NTOK, EE, EE, attb, Wo + (size_t)l * EE * EE, bo + l * EE, y);
        }
        // x = LN(x + y)
        ln_kernel<<<NTOK, EE>>>(x, y, ln1g + l * EE, ln1b + l * EE, x);
        // FFN1: relu([2048,256]@[256,1024] + b1)
        {
            dim3 grid((FFN + 63) / 64, (NTOK + 63) / 64);
            sgemm_kernel<64,64,16,4,4,true><<<grid, 256>>>(
                NTOK, FFN, EE, x, W1 + (size_t)l * EE * FFN, b1 + l * FFN, hbuf);
        }
        // FFN2: [2048,1024]@[1024,256] + b2
        {
            dim3 grid((EE + 63) / 64, (NTOK + 63) / 64);
            sgemm_kernel<64,64,16,4,4,false><<<grid, 256>>>(
                NTOK, EE, FFN, hbuf, W2 + (size_t)l * FFN * EE, b2 + l * EE, y);
        }
        // x = LN(x + y)
        ln_kernel<<<NTOK, EE>>>(x, y, ln2g + l * EE, ln2b + l * EE, x);
    }

    // Final LN
    ln_kernel<<<NTOK, EE>>>(x, nullptr, lnfg, lnfb, xf);

    // LM head: [2048,256]@[256,50257] + blm
    {
        dim3 grid((VOCAB + 127) / 128, (NTOK + 127) / 128);
        sgemm_kernel<128,128,16,8,8,false><<<grid, 256>>>(
            NTOK, VOCAB, EE, xf, Wlm, blm, out);
    }
}